// round 13
// baseline (speedup 1.0000x reference)
#include <cuda_runtime.h>
#include <math.h>

#define THREADS 256
#define RPT 4            // rows per thread per tile
#define TILE (THREADS * RPT)   // 1024 rows per block-tile
#define KC 32            // codebook size
#define DD 8             // codebook dim
#define NBLOCKS 592      // 148 SMs x 4 CTAs -> one resident wave

__device__ double g_sum;                 // zero-init at load; reset by last block each run
__device__ unsigned int g_counts[KC];
__device__ unsigned int g_done;

static __device__ __forceinline__ unsigned long long pk2(float lo, float hi) {
    unsigned long long r;
    asm("mov.b64 %0, {%1,%2};" : "=l"(r) : "f"(lo), "f"(hi));
    return r;
}
static __device__ __forceinline__ void upk2(unsigned long long v, float& lo, float& hi) {
    asm("mov.b64 {%0,%1}, %2;" : "=f"(lo), "=f"(hi) : "l"(v));
}
// packed f32x2 fma: d.lo = a.lo*b.lo + c.lo ; d.hi = a.hi*b.hi + c.hi
static __device__ __forceinline__ unsigned long long ffma2(unsigned long long a,
                                                           unsigned long long b,
                                                           unsigned long long c) {
    unsigned long long r;
    asm("fma.rn.f32x2 %0, %1, %2, %3;" : "=l"(r) : "l"(a), "l"(b), "l"(c));
    return r;
}

__global__ __launch_bounds__(THREADS) void vq_fused(
    const float* __restrict__ z, const float* __restrict__ cb,
    float* __restrict__ out, int nrows, long long ndelem, int write_scalars)
{
    // Dim-packed codebook: s_mk[k][0..7] = -2*c_d (natural order -> 2x LDS.128),
    // s_mk[k][8] = ||c||^2. Stride 12 floats keeps rows 16B-aligned.
    __shared__ float s_mk[KC][12];
    __shared__ float2 s_cpair[KC][5];    // raw code row, stride 5 -> bank-safe gather
    __shared__ unsigned int s_cnt[KC];
    __shared__ double s_red[THREADS / 32];
    __shared__ int s_islast;

    const int tid = threadIdx.x;
    const int lane = tid & 31;

    if (tid < KC) {
        float cn = 0.f;
#pragma unroll
        for (int d = 0; d < DD; d++) {
            float v = cb[tid * DD + d];
            s_mk[tid][d] = -2.f * v;
            cn = fmaf(v, v, cn);
            if ((d & 1) == 0) s_cpair[tid][d >> 1].x = v;
            else              s_cpair[tid][d >> 1].y = v;
        }
        s_mk[tid][8] = cn;
        s_cnt[tid] = 0u;
    }
    __syncthreads();

    const int ntiles = (nrows + TILE - 1) / TILE;
    float lsum = 0.f;

    for (int tile = blockIdx.x; tile < ntiles; tile += gridDim.x) {
        const long long tbase = (long long)tile * TILE + tid;
        const bool full = ((long long)tile * TILE + TILE) <= (long long)nrows;

        // ---- load RPT rows; float4 pairs ARE dim-packed f32x2 registers ----
        unsigned long long zr[RPT][4];
        bool valid[RPT];
#pragma unroll
        for (int r = 0; r < RPT; ++r) {
            long long row = tbase + (long long)r * THREADS;
            valid[r] = full || (row < nrows);
            long long lr = valid[r] ? row : 0;
            float4 a0 = *(const float4*)(z + lr * DD);
            float4 a1 = *(const float4*)(z + lr * DD + 4);
            ulonglong2 u0 = *(ulonglong2*)&a0;
            ulonglong2 u1 = *(ulonglong2*)&a1;
            zr[r][0] = u0.x; zr[r][1] = u0.y;
            zr[r][2] = u1.x; zr[r][3] = u1.y;
        }

        float best[RPT];
        int   bi[RPT];
#pragma unroll
        for (int i = 0; i < RPT; i++) { best[i] = 3.4e38f; bi[i] = 0; }

        // ---- argmin over 32 codes: dist-z2 = ||c||^2 + sum((-2c_d) z_d) ----
#pragma unroll 2
        for (int k = 0; k < KC; k++) {
            ulonglong2 A = *(const ulonglong2*)&s_mk[k][0];
            ulonglong2 B = *(const ulonglong2*)&s_mk[k][4];
            float cn = s_mk[k][8];
            unsigned long long init = pk2(cn, 0.f);
#pragma unroll
            for (int r = 0; r < RPT; r++) {
                unsigned long long acc = ffma2(zr[r][0], A.x, init);
                acc = ffma2(zr[r][1], A.y, acc);
                acc = ffma2(zr[r][2], B.x, acc);
                acc = ffma2(zr[r][3], B.y, acc);
                float lo, hi;
                upk2(acc, lo, hi);
                float d = lo + hi;
                if (d < best[r]) { best[r] = d; bi[r] = k; }
            }
        }

        // ---- epilogue: loss = Σ(c−z)^2 (exact), out = z + (c − z) ----
#pragma unroll
        for (int r = 0; r < RPT; r++) {
            if (!valid[r]) continue;
            const int b = bi[r];
            float2 c0 = s_cpair[b][0], c1 = s_cpair[b][1],
                   c2 = s_cpair[b][2], c3 = s_cpair[b][3];
            float zv[DD];
            upk2(zr[r][0], zv[0], zv[1]);
            upk2(zr[r][1], zv[2], zv[3]);
            upk2(zr[r][2], zv[4], zv[5]);
            upk2(zr[r][3], zv[6], zv[7]);
            float cv[DD] = {c0.x, c0.y, c1.x, c1.y, c2.x, c2.y, c3.x, c3.y};
            float ov[DD];
            float s = 0.f;
#pragma unroll
            for (int d = 0; d < DD; d++) {
                float df = cv[d] - zv[d];
                ov[d] = zv[d] + df;    // z + (z_q - z), matches reference FP order
                s = fmaf(df, df, s);
            }
            lsum += s;
            long long row = tbase + (long long)r * THREADS;
            *(float4*)(out + row * DD)     = make_float4(ov[0], ov[1], ov[2], ov[3]);
            *(float4*)(out + row * DD + 4) = make_float4(ov[4], ov[5], ov[6], ov[7]);
        }

        // warp-aggregated histogram (integer-exact)
#pragma unroll
        for (int r = 0; r < RPT; r++) {
            unsigned int key = valid[r] ? (unsigned int)bi[r] : 0xFFFFFFFFu;
            unsigned int grp = __match_any_sync(0xffffffffu, key);
            bool leader = ((grp & ((1u << lane) - 1u)) == 0u);
            if (valid[r] && leader) atomicAdd(&s_cnt[bi[r]], (unsigned int)__popc(grp));
        }
    }

    // ---- once per block: reductions -> global accumulators ----
#pragma unroll
    for (int off = 16; off; off >>= 1)
        lsum += __shfl_down_sync(0xffffffffu, lsum, off);
    if ((tid & 31) == 0) s_red[tid >> 5] = (double)lsum;
    __syncthreads();
    if (tid == 0) {
        double t = 0.0;
#pragma unroll
        for (int w = 0; w < THREADS / 32; w++) t += s_red[w];
        atomicAdd(&g_sum, t);
    }
    if (tid < KC) {
        unsigned int c = s_cnt[tid];
        if (c) atomicAdd(&g_counts[tid], c);
    }

    // ---- last-block finalize (threadfence + ticket pattern) ----
    __syncthreads();                 // all atomics above issued
    if (tid == 0) {
        __threadfence();             // make this block's contributions device-visible
        unsigned int ticket = atomicAdd(&g_done, 1u);
        s_islast = (ticket == gridDim.x - 1) ? 1 : 0;
    }
    __syncthreads();

    if (s_islast && tid < 32) {
        unsigned int cnt = g_counts[tid];
        double p = (double)cnt / (double)nrows;
        double term = p * log(p + 1e-10);
#pragma unroll
        for (int off = 16; off; off >>= 1)
            term += __shfl_down_sync(0xffffffffu, term, off);
        if (tid == 0) {
            double s = atomicAdd(&g_sum, 0.0);   // atomic read
            if (write_scalars) {
                out[ndelem]     = (float)((s * 1.25) / (double)ndelem);
                out[ndelem + 1] = (float)exp(-term);
            }
            g_sum = 0.0;                          // reset for next graph replay
        }
        g_counts[tid] = 0u;
        __threadfence();
        if (tid == 0) g_done = 0u;
    }
}

extern "C" void kernel_launch(void* const* d_in, const int* in_sizes, int n_in,
                              void* d_out, int out_size) {
    const float* z  = (const float*)d_in[0];
    const float* cb = (const float*)d_in[1];
    float* out = (float*)d_out;

    int nrows = in_sizes[0] / DD;
    long long ndelem = (long long)nrows * DD;
    int ntiles = (nrows + TILE - 1) / TILE;
    int blocks = ntiles < NBLOCKS ? ntiles : NBLOCKS;
    int write_scalars = ((long long)out_size >= ndelem + 2) ? 1 : 0;

    vq_fused<<<blocks, THREADS>>>(z, cb, out, nrows, ndelem, write_scalars);
}

// round 14
// speedup vs baseline: 1.7087x; 1.7087x over previous
#include <cuda_runtime.h>
#include <math.h>

#define THREADS 256
#define RPT 2                  // rows per thread per tile (double-buffered)
#define TILE (THREADS * RPT)   // 512 rows per block-tile
#define KC 32                  // codebook size
#define DD 8                   // codebook dim

__device__ double g_sum;                 // zero-init at load; reset by last block each run
__device__ unsigned int g_counts[KC];
__device__ unsigned int g_done;

static __device__ __forceinline__ unsigned long long pk2(float lo, float hi) {
    unsigned long long r;
    asm("mov.b64 %0, {%1,%2};" : "=l"(r) : "f"(lo), "f"(hi));
    return r;
}
static __device__ __forceinline__ void upk2(unsigned long long v, float& lo, float& hi) {
    asm("mov.b64 {%0,%1}, %2;" : "=f"(lo), "=f"(hi) : "l"(v));
}
// packed f32x2 fma: d.lo = a.lo*b.lo + c.lo ; d.hi = a.hi*b.hi + c.hi
static __device__ __forceinline__ unsigned long long ffma2(unsigned long long a,
                                                           unsigned long long b,
                                                           unsigned long long c) {
    unsigned long long r;
    asm("fma.rn.f32x2 %0, %1, %2, %3;" : "=l"(r) : "l"(a), "l"(b), "l"(c));
    return r;
}

struct TileBuf {
    unsigned long long zr[RPT][4];
    bool valid[RPT];
};

static __device__ __forceinline__ void load_tile(
    const float* __restrict__ z, long long tile, int tid, int nrows, TileBuf& b)
{
    const long long tbase = tile * TILE + tid;
#pragma unroll
    for (int r = 0; r < RPT; ++r) {
        long long row = tbase + (long long)r * THREADS;
        b.valid[r] = (row < nrows);
        long long lr = b.valid[r] ? row : 0;
        float4 a0 = *(const float4*)(z + lr * DD);
        float4 a1 = *(const float4*)(z + lr * DD + 4);
        ulonglong2 u0 = *(ulonglong2*)&a0;   // (z0,z1),(z2,z3)
        ulonglong2 u1 = *(ulonglong2*)&a1;   // (z4,z5),(z6,z7)
        b.zr[r][0] = u0.x; b.zr[r][1] = u0.y;
        b.zr[r][2] = u1.x; b.zr[r][3] = u1.y;
    }
}

static __device__ __forceinline__ void process_tile(
    const float (*s_mk)[12], const float2 (*s_cpair)[5], unsigned int* s_cnt,
    float* __restrict__ out, long long tile, int tid, int lane,
    const TileBuf& b, float& lsum)
{
    const long long tbase = tile * TILE + tid;

    float best[RPT];
    int   bi[RPT];
#pragma unroll
    for (int i = 0; i < RPT; i++) { best[i] = 3.4e38f; bi[i] = 0; }

    // argmin over 32 codes: dist-z2 = ||c||^2 + sum((-2c_d) z_d), dim-packed
#pragma unroll 4
    for (int k = 0; k < KC; k++) {
        ulonglong2 A = *(const ulonglong2*)&s_mk[k][0];
        ulonglong2 B = *(const ulonglong2*)&s_mk[k][4];
        float cn = s_mk[k][8];
        unsigned long long init = pk2(cn, 0.f);
#pragma unroll
        for (int r = 0; r < RPT; r++) {
            unsigned long long acc = ffma2(b.zr[r][0], A.x, init);
            acc = ffma2(b.zr[r][1], A.y, acc);
            acc = ffma2(b.zr[r][2], B.x, acc);
            acc = ffma2(b.zr[r][3], B.y, acc);
            float lo, hi;
            upk2(acc, lo, hi);
            float d = lo + hi;
            if (d < best[r]) { best[r] = d; bi[r] = k; }
        }
    }

    // epilogue: loss = sum((c-z)^2) exact, out = z + (c - z)
#pragma unroll
    for (int r = 0; r < RPT; r++) {
        if (!b.valid[r]) continue;
        const int bk = bi[r];
        float2 c0 = s_cpair[bk][0], c1 = s_cpair[bk][1],
               c2 = s_cpair[bk][2], c3 = s_cpair[bk][3];
        float zv[DD];
        upk2(b.zr[r][0], zv[0], zv[1]);
        upk2(b.zr[r][1], zv[2], zv[3]);
        upk2(b.zr[r][2], zv[4], zv[5]);
        upk2(b.zr[r][3], zv[6], zv[7]);
        float cv[DD] = {c0.x, c0.y, c1.x, c1.y, c2.x, c2.y, c3.x, c3.y};
        float ov[DD];
        float s = 0.f;
#pragma unroll
        for (int d = 0; d < DD; d++) {
            float df = cv[d] - zv[d];
            ov[d] = zv[d] + df;     // z + (z_q - z), matches reference FP order
            s = fmaf(df, df, s);
        }
        lsum += s;
        long long row = tbase + (long long)r * THREADS;
        *(float4*)(out + row * DD)     = make_float4(ov[0], ov[1], ov[2], ov[3]);
        *(float4*)(out + row * DD + 4) = make_float4(ov[4], ov[5], ov[6], ov[7]);
    }

    // warp-aggregated histogram (integer-exact)
#pragma unroll
    for (int r = 0; r < RPT; r++) {
        unsigned int key = b.valid[r] ? (unsigned int)bi[r] : 0xFFFFFFFFu;
        unsigned int grp = __match_any_sync(0xffffffffu, key);
        bool leader = ((grp & ((1u << lane) - 1u)) == 0u);
        if (b.valid[r] && leader) atomicAdd(&s_cnt[bi[r]], (unsigned int)__popc(grp));
    }
}

__global__ __launch_bounds__(THREADS) void vq_fused(
    const float* __restrict__ z, const float* __restrict__ cb,
    float* __restrict__ out, int nrows, long long ndelem, int write_scalars)
{
    __shared__ float s_mk[KC][12];       // [0..7]=-2c_d, [8]=||c||^2, 16B-aligned rows
    __shared__ float2 s_cpair[KC][5];    // raw code row, stride 5 -> bank-safe gather
    __shared__ unsigned int s_cnt[KC];
    __shared__ double s_red[THREADS / 32];
    __shared__ int s_islast;

    const int tid = threadIdx.x;
    const int lane = tid & 31;

    if (tid < KC) {
        float cn = 0.f;
#pragma unroll
        for (int d = 0; d < DD; d++) {
            float v = cb[tid * DD + d];
            s_mk[tid][d] = -2.f * v;
            cn = fmaf(v, v, cn);
            if ((d & 1) == 0) s_cpair[tid][d >> 1].x = v;
            else              s_cpair[tid][d >> 1].y = v;
        }
        s_mk[tid][8] = cn;
        s_cnt[tid] = 0u;
    }
    __syncthreads();

    const long long ntiles = ((long long)nrows + TILE - 1) / TILE;
    const long long stride = gridDim.x;
    float lsum = 0.f;

    // ---- software-pipelined persistent loop: prefetch t+stride while computing t ----
    TileBuf bufA, bufB;
    long long tile = blockIdx.x;
    if (tile < ntiles) {
        load_tile(z, tile, tid, nrows, bufA);
        while (true) {
            // stage A: compute bufA, prefetch into bufB
            long long nxt = tile + stride;
            if (nxt < ntiles) load_tile(z, nxt, tid, nrows, bufB);
            process_tile(s_mk, s_cpair, s_cnt, out, tile, tid, lane, bufA, lsum);
            tile = nxt;
            if (tile >= ntiles) break;
            // stage B: compute bufB, prefetch into bufA
            nxt = tile + stride;
            if (nxt < ntiles) load_tile(z, nxt, tid, nrows, bufA);
            process_tile(s_mk, s_cpair, s_cnt, out, tile, tid, lane, bufB, lsum);
            tile = nxt;
            if (tile >= ntiles) break;
        }
    }

    // ---- once per block: reductions -> global accumulators ----
#pragma unroll
    for (int off = 16; off; off >>= 1)
        lsum += __shfl_down_sync(0xffffffffu, lsum, off);
    if ((tid & 31) == 0) s_red[tid >> 5] = (double)lsum;
    __syncthreads();
    if (tid == 0) {
        double t = 0.0;
#pragma unroll
        for (int w = 0; w < THREADS / 32; w++) t += s_red[w];
        atomicAdd(&g_sum, t);
    }
    if (tid < KC) {
        unsigned int c = s_cnt[tid];
        if (c) atomicAdd(&g_counts[tid], c);
    }

    // ---- last-block finalize (threadfence + ticket pattern) ----
    __syncthreads();                 // all atomics above issued
    if (tid == 0) {
        __threadfence();             // make this block's contributions device-visible
        unsigned int ticket = atomicAdd(&g_done, 1u);
        s_islast = (ticket == gridDim.x - 1) ? 1 : 0;
    }
    __syncthreads();

    if (s_islast && tid < 32) {
        unsigned int cnt = g_counts[tid];
        double p = (double)cnt / (double)nrows;
        double term = p * log(p + 1e-10);
#pragma unroll
        for (int off = 16; off; off >>= 1)
            term += __shfl_down_sync(0xffffffffu, term, off);
        if (tid == 0) {
            double s = atomicAdd(&g_sum, 0.0);   // atomic read
            if (write_scalars) {
                out[ndelem]     = (float)((s * 1.25) / (double)ndelem);
                out[ndelem + 1] = (float)exp(-term);
            }
            g_sum = 0.0;                          // reset for next graph replay
        }
        g_counts[tid] = 0u;
        __threadfence();
        if (tid == 0) g_done = 0u;
    }
}

extern "C" void kernel_launch(void* const* d_in, const int* in_sizes, int n_in,
                              void* d_out, int out_size) {
    const float* z  = (const float*)d_in[0];
    const float* cb = (const float*)d_in[1];
    float* out = (float*)d_out;

    int nrows = in_sizes[0] / DD;
    long long ndelem = (long long)nrows * DD;
    long long ntiles = ((long long)nrows + TILE - 1) / TILE;
    int write_scalars = ((long long)out_size >= ndelem + 2) ? 1 : 0;

    // exact one-wave grid: resident CTAs per SM x SM count (deterministic per device)
    int cta_per_sm = 0, nsm = 0;
    cudaOccupancyMaxActiveBlocksPerMultiprocessor(&cta_per_sm, vq_fused, THREADS, 0);
    cudaDeviceGetAttribute(&nsm, cudaDevAttrMultiProcessorCount, 0);
    if (cta_per_sm <= 0) cta_per_sm = 3;
    if (nsm <= 0) nsm = 148;
    long long blocks = (long long)cta_per_sm * nsm;
    if (blocks > ntiles) blocks = ntiles;

    vq_fused<<<(int)blocks, THREADS>>>(z, cb, out, nrows, ndelem, write_scalars);
}